// round 12
// baseline (speedup 1.0000x reference)
#include <cuda_runtime.h>

// MPJRDLayer fused forward — two-kernel: 4-row/warp spikes + parallel rates.
// x:     [B=128, N=1024, D=8, S=64] fp32 (512 contiguous floats per (b,n))
// W:     [1024, 512] fp32;  theta, r_hat: [1024]
// out:   spikes [B*N] ++ rates [N] ++ thetas [N] ++ r_hats [N]

#define NB   128
#define NN   1024
#define DS   512

// ── Kernel 1: one warp computes spikes for (n, b0..b0+3). ──
// 32768 warps = 4096 blocks x 8 warps.
__global__ __launch_bounds__(256)
void mpjrd_spikes_kernel(const float* __restrict__ x,
                         const float* __restrict__ W,
                         const float* __restrict__ theta,
                         float* __restrict__ out)
{
    const int warp = threadIdx.x >> 5;
    const int lane = threadIdx.x & 31;
    const int id   = blockIdx.x * 8 + warp;      // 0 .. 32767
    const int n    = id & (NN - 1);
    const int b0   = (id >> 10) << 2;            // 0,4,...,124

    const float4* Wv = reinterpret_cast<const float4*>(W + (size_t)n * DS);
    const float4 w0 = Wv[0 * 32 + lane];
    const float4 w1 = Wv[1 * 32 + lane];
    const float4 w2 = Wv[2 * 32 + lane];
    const float4 w3 = Wv[3 * 32 + lane];

    float acc[4];

    #pragma unroll
    for (int r = 0; r < 4; ++r) {
        const float4* xr = reinterpret_cast<const float4*>(
            x + ((size_t)(b0 + r) * NN + n) * DS);
        const float4 v0 = xr[0 * 32 + lane];
        const float4 v1 = xr[1 * 32 + lane];
        const float4 v2 = xr[2 * 32 + lane];
        const float4 v3 = xr[3 * 32 + lane];

        float a = 0.0f;
        a = fmaf(v0.x, w0.x, a); a = fmaf(v0.y, w0.y, a);
        a = fmaf(v0.z, w0.z, a); a = fmaf(v0.w, w0.w, a);
        a = fmaf(v1.x, w1.x, a); a = fmaf(v1.y, w1.y, a);
        a = fmaf(v1.z, w1.z, a); a = fmaf(v1.w, w1.w, a);
        a = fmaf(v2.x, w2.x, a); a = fmaf(v2.y, w2.y, a);
        a = fmaf(v2.z, w2.z, a); a = fmaf(v2.w, w2.w, a);
        a = fmaf(v3.x, w3.x, a); a = fmaf(v3.y, w3.y, a);
        a = fmaf(v3.z, w3.z, a); a = fmaf(v3.w, w3.w, a);
        acc[r] = a;
    }

    #pragma unroll
    for (int off = 16; off; off >>= 1) {
        acc[0] += __shfl_xor_sync(0xFFFFFFFFu, acc[0], off);
        acc[1] += __shfl_xor_sync(0xFFFFFFFFu, acc[1], off);
        acc[2] += __shfl_xor_sync(0xFFFFFFFFu, acc[2], off);
        acc[3] += __shfl_xor_sync(0xFFFFFFFFu, acc[3], off);
    }

    if (lane == 0) {
        const float th = theta[n];
        #pragma unroll
        for (int r = 0; r < 4; ++r)
            out[(size_t)(b0 + r) * NN + n] = (acc[r] >= th) ? 1.0f : 0.0f;
    }
}

// ── Kernel 2: parallel column-sum of spikes + homeostatic update. ──
// 32 blocks x 256 threads. Block g owns neurons [32g, 32g+32).
// Warp w sums b-chunk [16w, 16w+16); lane = local neuron → coalesced loads.
__global__ __launch_bounds__(256)
void mpjrd_rates_kernel(const float* __restrict__ theta,
                        const float* __restrict__ r_hat,
                        float* __restrict__ out)
{
    __shared__ float part[8][32];   // [warp][local neuron]

    const int warp = threadIdx.x >> 5;
    const int lane = threadIdx.x & 31;
    const int n    = blockIdx.x * 32 + lane;

    const float* sp = out + n + (size_t)(warp * 16) * NN;
    float acc = 0.0f;
    #pragma unroll
    for (int i = 0; i < 16; ++i)
        acc += sp[(size_t)i * NN];
    part[warp][lane] = acc;
    __syncthreads();

    if (warp == 0) {
        float c = 0.0f;
        #pragma unroll
        for (int w = 0; w < 8; ++w) c += part[w][lane];

        const float rate = c * (1.0f / 128.0f);
        const float rh   = 0.95f * __ldg(r_hat + n) + 0.05f * rate;
        const float thn  = __ldg(theta + n) + 0.1f * (rh - 0.1f);
        out[NB * NN + n]          = rate;
        out[NB * NN + NN + n]     = thn;
        out[NB * NN + 2 * NN + n] = rh;
    }
}

extern "C" void kernel_launch(void* const* d_in, const int* in_sizes, int n_in,
                              void* d_out, int out_size)
{
    const float* x     = (const float*)d_in[0];
    const float* W     = (const float*)d_in[1];
    const float* theta = (const float*)d_in[2];
    const float* r_hat = (const float*)d_in[3];
    float* out = (float*)d_out;

    mpjrd_spikes_kernel<<<4096, 256>>>(x, W, theta, out);
    mpjrd_rates_kernel<<<32, 256>>>(theta, r_hat, out);
}

// round 13
// speedup vs baseline: 1.0809x; 1.0809x over previous
#include <cuda_runtime.h>

// MPJRDLayer fused forward — 2-row/warp spikes with in-kernel count atomics
// + tiny 4KB finalize kernel.
// x:     [B=128, N=1024, D=8, S=64] fp32 (512 contiguous floats per (b,n))
// W:     [1024, 512] fp32;  theta, r_hat: [1024]
// out:   spikes [B*N] ++ rates [N] ++ thetas [N] ++ r_hats [N]

#define NB   128
#define NN   1024
#define DS   512

__device__ float g_cnt[NN];   // zero-initialized at load; reset by finalize each call

// ── Kernel 1: one warp computes spikes for (n, b0) and (n, b0+1). ──
// 65536 warps = 8192 blocks x 8 warps.  (R3 streaming core + lane0 atomic.)
__global__ __launch_bounds__(256)
void mpjrd_spikes_kernel(const float* __restrict__ x,
                         const float* __restrict__ W,
                         const float* __restrict__ theta,
                         float* __restrict__ out)
{
    const int warp = threadIdx.x >> 5;
    const int lane = threadIdx.x & 31;
    const int id   = blockIdx.x * 8 + warp;      // 0 .. 65535
    const int n    = id & (NN - 1);
    const int b0   = (id >> 10) << 1;            // 0,2,...,126
    const int b1   = b0 + 1;

    const float4* Wv = reinterpret_cast<const float4*>(W + (size_t)n * DS);
    const float4 w0 = Wv[0 * 32 + lane];
    const float4 w1 = Wv[1 * 32 + lane];
    const float4 w2 = Wv[2 * 32 + lane];
    const float4 w3 = Wv[3 * 32 + lane];

    const float4* xa = reinterpret_cast<const float4*>(x + ((size_t)b0 * NN + n) * DS);
    const float4* xb = reinterpret_cast<const float4*>(x + ((size_t)b1 * NN + n) * DS);

    const float4 a0 = xa[0 * 32 + lane];
    const float4 a1 = xa[1 * 32 + lane];
    const float4 a2 = xa[2 * 32 + lane];
    const float4 a3 = xa[3 * 32 + lane];
    const float4 c0 = xb[0 * 32 + lane];
    const float4 c1 = xb[1 * 32 + lane];
    const float4 c2 = xb[2 * 32 + lane];
    const float4 c3 = xb[3 * 32 + lane];

    float accA = 0.0f, accB = 0.0f;
    accA = fmaf(a0.x, w0.x, accA); accA = fmaf(a0.y, w0.y, accA);
    accA = fmaf(a0.z, w0.z, accA); accA = fmaf(a0.w, w0.w, accA);
    accA = fmaf(a1.x, w1.x, accA); accA = fmaf(a1.y, w1.y, accA);
    accA = fmaf(a1.z, w1.z, accA); accA = fmaf(a1.w, w1.w, accA);
    accA = fmaf(a2.x, w2.x, accA); accA = fmaf(a2.y, w2.y, accA);
    accA = fmaf(a2.z, w2.z, accA); accA = fmaf(a2.w, w2.w, accA);
    accA = fmaf(a3.x, w3.x, accA); accA = fmaf(a3.y, w3.y, accA);
    accA = fmaf(a3.z, w3.z, accA); accA = fmaf(a3.w, w3.w, accA);

    accB = fmaf(c0.x, w0.x, accB); accB = fmaf(c0.y, w0.y, accB);
    accB = fmaf(c0.z, w0.z, accB); accB = fmaf(c0.w, w0.w, accB);
    accB = fmaf(c1.x, w1.x, accB); accB = fmaf(c1.y, w1.y, accB);
    accB = fmaf(c1.z, w1.z, accB); accB = fmaf(c1.w, w1.w, accB);
    accB = fmaf(c2.x, w2.x, accB); accB = fmaf(c2.y, w2.y, accB);
    accB = fmaf(c2.z, w2.z, accB); accB = fmaf(c2.w, w2.w, accB);
    accB = fmaf(c3.x, w3.x, accB); accB = fmaf(c3.y, w3.y, accB);
    accB = fmaf(c3.z, w3.z, accB); accB = fmaf(c3.w, w3.w, accB);

    #pragma unroll
    for (int off = 16; off; off >>= 1) {
        accA += __shfl_xor_sync(0xFFFFFFFFu, accA, off);
        accB += __shfl_xor_sync(0xFFFFFFFFu, accB, off);
    }

    if (lane == 0) {
        const float th = theta[n];
        const float sA = (accA >= th) ? 1.0f : 0.0f;
        const float sB = (accB >= th) ? 1.0f : 0.0f;
        out[(size_t)b0 * NN + n] = sA;
        out[(size_t)b1 * NN + n] = sB;
        const float s = sA + sB;
        if (s != 0.0f) atomicAdd(&g_cnt[n], s);   // integer-valued: order-invariant
    }
}

// ── Kernel 2: finalize from g_cnt (4 KB) — launch-overhead bound. ──
// 1 block x 1024 threads; also resets g_cnt for the next graph replay.
__global__ __launch_bounds__(1024)
void mpjrd_finalize_kernel(const float* __restrict__ theta,
                           const float* __restrict__ r_hat,
                           float* __restrict__ out)
{
    const int n = threadIdx.x;
    const float c = g_cnt[n];
    g_cnt[n] = 0.0f;                              // replay-safe reset

    const float rate = c * (1.0f / 128.0f);
    const float rh   = 0.95f * __ldg(r_hat + n) + 0.05f * rate;
    const float thn  = __ldg(theta + n) + 0.1f * (rh - 0.1f);
    out[NB * NN + n]          = rate;
    out[NB * NN + NN + n]     = thn;
    out[NB * NN + 2 * NN + n] = rh;
}

extern "C" void kernel_launch(void* const* d_in, const int* in_sizes, int n_in,
                              void* d_out, int out_size)
{
    const float* x     = (const float*)d_in[0];
    const float* W     = (const float*)d_in[1];
    const float* theta = (const float*)d_in[2];
    const float* r_hat = (const float*)d_in[3];
    float* out = (float*)d_out;

    mpjrd_spikes_kernel<<<8192, 256>>>(x, W, theta, out);
    mpjrd_finalize_kernel<<<1, 1024>>>(theta, r_hat, out);
}